// round 11
// baseline (speedup 1.0000x reference)
#include <cuda_runtime.h>
#include <cuda_fp16.h>
#include <math.h>
#include <stdint.h>

#define BB 2
#define CC 768
#define TT 2048
#define II 768
#define HH 12
#define DH 64
#define SS 16
#define CTXD 512
#define FFD 3072
#define DEPTH 2
#define KSZ 9

typedef long long ll;

#define LDS_ROW 40              // halfs per smem tile row (32 + 8 pad)
#define STAGE_HALFS (128 * LDS_ROW)
#define NSTAGE 3
#define GK_SMEM_BYTES (2 * NSTAGE * STAGE_HALFS * 2)

// big-tile GEMM (256M x 128N)
#define BG_A_STAGE (256 * LDS_ROW)
#define BG_B_STAGE (128 * LDS_ROW)
#define BG_SMEM_BYTES (NSTAGE * (BG_A_STAGE + BG_B_STAGE) * 2)

// flash-attention tiles
#define FA_BR 128
#define FA_BC 128
#define QROW 72
#define FA_TILE (128 * QROW)
#define FA_NST 3
#define FA_SMEM_BYTES ((1 + 2 * FA_NST) * FA_TILE * 2)
#define S3 (3 * II)             // packed qkv row stride

// ================= scratch ======================================================
__device__ __half g_gth[BB * (ll)TT * CC];
__device__ float  g_h  [BB * (ll)TT * II];
__device__ __half g_hc [BB * (ll)TT * II];
__device__ __half g_y  [BB * (ll)TT * II];
__device__ __half g_q  [BB * (ll)TT * II];
__device__ __half g_qkv[BB * (ll)TT * S3];
__device__ __half g_ao [BB * (ll)TT * II];
__device__ __half g_kcv[BB * SS * 2 * II];
__device__ __half g_f1 [BB * (ll)TT * FFD];
__device__ float  g_po [BB * (ll)TT * CC];
__device__ __half g_wT [16 * (ll)II * II];
__device__ __half g_w2kv[DEPTH * 2 * (ll)II * CTXD];   // dense fused cross K|V weights
__device__ __half g_pinw [(ll)II * CC];
__device__ __half g_poutw[(ll)CC * II];
__device__ __half g_ctxh [BB * SS * CTXD];
__device__ __half g_wt1[DEPTH * (ll)KSZ * FFD * II];
__device__ __half g_wt2[DEPTH * (ll)KSZ * II * FFD];
__device__ float  g_gstats[BB * 32 * 2];

// ================= helpers ======================================================
__device__ __forceinline__ uint32_t smem_u32(const void* p) {
    uint32_t a;
    asm("{ .reg .u64 t; cvta.to.shared.u64 t, %1; cvt.u32.u64 %0, t; }" : "=r"(a) : "l"(p));
    return a;
}
__device__ __forceinline__ void cp16(uint32_t dst, const void* src) {
    asm volatile("cp.async.cg.shared.global [%0], [%1], 16;" :: "r"(dst), "l"(src));
}
#define CP_COMMIT() asm volatile("cp.async.commit_group;" ::: "memory")
#define CP_WAIT(n)  asm volatile("cp.async.wait_group %0;" :: "n"(n) : "memory")

__device__ __forceinline__ void ldsm_x4(unsigned* r, uint32_t addr) {
    asm volatile("ldmatrix.sync.aligned.m8n8.x4.shared.b16 {%0,%1,%2,%3}, [%4];"
                 : "=r"(r[0]), "=r"(r[1]), "=r"(r[2]), "=r"(r[3]) : "r"(addr));
}
__device__ __forceinline__ void ldsm_x4_t(unsigned* r, uint32_t addr) {
    asm volatile("ldmatrix.sync.aligned.m8n8.x4.trans.shared.b16 {%0,%1,%2,%3}, [%4];"
                 : "=r"(r[0]), "=r"(r[1]), "=r"(r[2]), "=r"(r[3]) : "r"(addr));
}
__device__ __forceinline__ void mma_f16(float* c, const unsigned* a, const unsigned* b) {
    asm volatile(
        "mma.sync.aligned.m16n8k16.row.col.f32.f16.f16.f32 "
        "{%0,%1,%2,%3}, {%4,%5,%6,%7}, {%8,%9}, {%0,%1,%2,%3};"
        : "+f"(c[0]), "+f"(c[1]), "+f"(c[2]), "+f"(c[3])
        : "r"(a[0]), "r"(a[1]), "r"(a[2]), "r"(a[3]), "r"(b[0]), "r"(b[1]));
}

// ================= generic fp16 GEMM (128x128) ==================================
__global__ void __launch_bounds__(256, 2)
gemm_h_kernel(const __half* __restrict__ A, ll sAb, ll sAh, int lda,
              const __half* __restrict__ Bm, ll sBb, ll sBh, int ldb,
              void* __restrict__ Cm, ll sCb, ll sCh, int ldc, int outHalf,
              const float* __restrict__ bias,
              const float* __restrict__ res, ll sRb, ll sRh, int ldr,
              int M, int N, int K, int Kinner,
              float alpha, int zdiv, int biasMode, int act)
{
    extern __shared__ __half dynsm[];
    __half* smA = dynsm;
    __half* smB = dynsm + NSTAGE * STAGE_HALFS;
    uint32_t suA = smem_u32(smA);
    uint32_t suB = smem_u32(smB);

    int tid = threadIdx.x;
    int lane = tid & 31, wid = tid >> 5;
    int wm = wid >> 1, wn = wid & 1;
    int g = lane >> 2, c = lane & 3;
    int z = blockIdx.z, zb = z / zdiv, zh = z % zdiv;
    const __half* Ab = A + zb * sAb + zh * sAh;
    const __half* Bb = Bm + zb * sBb + zh * sBh;
    int m0 = blockIdx.y * 128, n0 = blockIdx.x * 128;
    int lr = tid >> 1;
    int lkh = (tid & 1) * 16;
    ll planeB = (ll)N * Kinner;

    uint32_t aOff = ((uint32_t)((wm * 32 + (lane & 15)) * LDS_ROW + ((lane >> 4) * 8))) * 2;
    uint32_t bOff = ((uint32_t)((wn * 64 + (lane & 7) + ((lane & 16) >> 1)) * LDS_ROW + (lane & 8))) * 2;

    float acc[2][8][4];
#pragma unroll
    for (int i = 0; i < 2; i++)
#pragma unroll
        for (int j = 0; j < 8; j++)
#pragma unroll
            for (int e = 0; e < 4; e++) acc[i][j][e] = 0.f;

    auto issue_chunk = [&](int cidx, int slot) {
        int k0 = cidx * 32;
        int tap = 0, koff = k0, shift = 0;
        if (Kinner > 0) { tap = k0 / Kinner; koff = k0 - tap * Kinner; shift = tap - (KSZ / 2); }
        {
            int m = m0 + lr, sr = m + shift;
            bool ok = (m < M) && (sr >= 0) && (sr < M);
            uint32_t da = suA + (slot * STAGE_HALFS + lr * LDS_ROW + lkh) * 2;
            if (ok) {
                const __half* sp = Ab + (ll)sr * lda + koff + lkh;
                cp16(da, sp);
                cp16(da + 16, sp + 8);
            } else {
                *(uint4*)&smA[slot * STAGE_HALFS + lr * LDS_ROW + lkh] = make_uint4(0, 0, 0, 0);
                *(uint4*)&smA[slot * STAGE_HALFS + lr * LDS_ROW + lkh + 8] = make_uint4(0, 0, 0, 0);
            }
        }
        {
            int n = n0 + lr;
            bool ok = (n < N);
            uint32_t db = suB + (slot * STAGE_HALFS + lr * LDS_ROW + lkh) * 2;
            if (ok) {
                const __half* sp = Bb + (ll)tap * planeB + (ll)n * ldb + koff + lkh;
                cp16(db, sp);
                cp16(db + 16, sp + 8);
            } else {
                *(uint4*)&smB[slot * STAGE_HALFS + lr * LDS_ROW + lkh] = make_uint4(0, 0, 0, 0);
                *(uint4*)&smB[slot * STAGE_HALFS + lr * LDS_ROW + lkh + 8] = make_uint4(0, 0, 0, 0);
            }
        }
    };

    int NC = K / 32;
    issue_chunk(0, 0);
    CP_COMMIT();
    if (NC > 1) issue_chunk(1, 1);
    CP_COMMIT();

    for (int i = 0; i < NC; i++) {
        CP_WAIT(1);
        __syncthreads();
        if (i + 2 < NC) issue_chunk(i + 2, (i + 2) % NSTAGE);
        CP_COMMIT();

        uint32_t aBase = suA + (uint32_t)((i % NSTAGE) * STAGE_HALFS) * 2 + aOff;
        uint32_t bBase = suB + (uint32_t)((i % NSTAGE) * STAGE_HALFS) * 2 + bOff;
#pragma unroll
        for (int ks = 0; ks < 2; ks++) {
            uint32_t kbb = ks * 32;
            unsigned af[2][4], bf[8][2];
#pragma unroll
            for (int mt = 0; mt < 2; mt++)
                ldsm_x4(af[mt], aBase + mt * (16 * LDS_ROW * 2) + kbb);
#pragma unroll
            for (int j = 0; j < 4; j++) {
                unsigned rr[4];
                ldsm_x4(rr, bBase + j * (16 * LDS_ROW * 2) + kbb);
                bf[2 * j][0] = rr[0]; bf[2 * j][1] = rr[1];
                bf[2 * j + 1][0] = rr[2]; bf[2 * j + 1][1] = rr[3];
            }
#pragma unroll
            for (int mt = 0; mt < 2; mt++)
#pragma unroll
                for (int nt = 0; nt < 8; nt++)
                    mma_f16(acc[mt][nt], af[mt], bf[nt]);
        }
    }

    ll cbase = zb * sCb + zh * sCh;
    float* Cf = (float*)Cm + cbase;
    __half* Ch = (__half*)Cm + cbase;
    const float* Rb2 = res ? (res + zb * sRb + zh * sRh) : (const float*)0;
#pragma unroll
    for (int mt = 0; mt < 2; mt++) {
#pragma unroll
        for (int hf = 0; hf < 2; hf++) {
            int m = m0 + wm * 32 + mt * 16 + g + hf * 8;
            if (m >= M) continue;
            float bm = (biasMode == 2) ? bias[m] : 0.f;
            const float* rr = Rb2 ? (Rb2 + (ll)m * ldr) : (const float*)0;
#pragma unroll
            for (int nt = 0; nt < 8; nt++) {
#pragma unroll
                for (int e = 0; e < 2; e++) {
                    int n = n0 + wn * 64 + nt * 8 + c * 2 + e;
                    if (n >= N) continue;
                    float v = acc[mt][nt][hf * 2 + e] * alpha + bm;
                    if (biasMode == 1) v += bias[n];
                    if (rr) v += rr[n];
                    if (act) v = v * normcdff(v);
                    if (outHalf) Ch[(ll)m * ldc + n] = __float2half_rn(v);
                    else         Cf[(ll)m * ldc + n] = v;
                }
            }
        }
    }
}

// ================= big-tile fp16 GEMM (256M x 128N, warp 64x64) =================
__global__ void __launch_bounds__(256, 1)
gemm_big_kernel(const __half* __restrict__ A, ll sAb, int lda,
                const __half* __restrict__ Bm, ll sBb, int ldb,
                void* __restrict__ Cm, ll sCb, int ldc, int outHalf,
                const float* __restrict__ bias,
                int M, int N, int K, int Kinner,
                float alpha, int biasMode, int act)
{
    extern __shared__ __half dynsm[];
    __half* smA = dynsm;
    __half* smB = dynsm + NSTAGE * BG_A_STAGE;
    uint32_t suA = smem_u32(smA);
    uint32_t suB = smem_u32(smB);

    int tid = threadIdx.x;
    int lane = tid & 31, wid = tid >> 5;
    int wm = wid >> 1, wn = wid & 1;
    int g = lane >> 2, c = lane & 3;
    int zb = blockIdx.z;
    const __half* Ab = A + zb * sAb;
    const __half* Bb = Bm + zb * sBb;
    int m0 = blockIdx.y * 256, n0 = blockIdx.x * 128;
    int lr = tid >> 1;
    int lkh = (tid & 1) * 16;
    ll planeB = (ll)N * Kinner;

    uint32_t aOff = ((uint32_t)((wm * 64 + (lane & 15)) * LDS_ROW + ((lane >> 4) * 8))) * 2;
    uint32_t bOff = ((uint32_t)((wn * 64 + (lane & 7) + ((lane & 16) >> 1)) * LDS_ROW + (lane & 8))) * 2;

    float acc[4][8][4];
#pragma unroll
    for (int i = 0; i < 4; i++)
#pragma unroll
        for (int j = 0; j < 8; j++)
#pragma unroll
            for (int e = 0; e < 4; e++) acc[i][j][e] = 0.f;

    auto issue_chunk = [&](int cidx, int slot) {
        int k0 = cidx * 32;
        int tap = 0, koff = k0, shift = 0;
        if (Kinner > 0) { tap = k0 / Kinner; koff = k0 - tap * Kinner; shift = tap - (KSZ / 2); }
#pragma unroll
        for (int r2 = 0; r2 < 2; r2++) {
            int row = lr + r2 * 128;
            int m = m0 + row, sr = m + shift;
            bool ok = (m < M) && (sr >= 0) && (sr < M);
            uint32_t da = suA + (slot * BG_A_STAGE + row * LDS_ROW + lkh) * 2;
            if (ok) {
                const __half* sp = Ab + (ll)sr * lda + koff + lkh;
                cp16(da, sp);
                cp16(da + 16, sp + 8);
            } else {
                *(uint4*)&smA[slot * BG_A_STAGE + row * LDS_ROW + lkh] = make_uint4(0, 0, 0, 0);
                *(uint4*)&smA[slot * BG_A_STAGE + row * LDS_ROW + lkh + 8] = make_uint4(0, 0, 0, 0);
            }
        }
        {
            int n = n0 + lr;
            bool ok = (n < N);
            uint32_t db = suB + (slot * BG_B_STAGE + lr * LDS_ROW + lkh) * 2;
            if (ok) {
                const __half* sp = Bb + (ll)tap * planeB + (ll)n * ldb + koff + lkh;
                cp16(db, sp);
                cp16(db + 16, sp + 8);
            } else {
                *(uint4*)&smB[slot * BG_B_STAGE + lr * LDS_ROW + lkh] = make_uint4(0, 0, 0, 0);
                *(uint4*)&smB[slot * BG_B_STAGE + lr * LDS_ROW + lkh + 8] = make_uint4(0, 0, 0, 0);
            }
        }
    };

    int NC = K / 32;
    issue_chunk(0, 0);
    CP_COMMIT();
    if (NC > 1) issue_chunk(1, 1);
    CP_COMMIT();

    for (int i = 0; i < NC; i++) {
        CP_WAIT(1);
        __syncthreads();
        if (i + 2 < NC) issue_chunk(i + 2, (i + 2) % NSTAGE);
        CP_COMMIT();

        uint32_t aBase = suA + (uint32_t)((i % NSTAGE) * BG_A_STAGE) * 2 + aOff;
        uint32_t bBase = suB + (uint32_t)((i % NSTAGE) * BG_B_STAGE) * 2 + bOff;
#pragma unroll
        for (int ks = 0; ks < 2; ks++) {
            uint32_t kbb = ks * 32;
            unsigned af[4][4], bf[8][2];
#pragma unroll
            for (int mt = 0; mt < 4; mt++)
                ldsm_x4(af[mt], aBase + mt * (16 * LDS_ROW * 2) + kbb);
#pragma unroll
            for (int j = 0; j < 4; j++) {
                unsigned rr[4];
                ldsm_x4(rr, bBase + j * (16 * LDS_ROW * 2) + kbb);
                bf[2 * j][0] = rr[0]; bf[2 * j][1] = rr[1];
                bf[2 * j + 1][0] = rr[2]; bf[2 * j + 1][1] = rr[3];
            }
#pragma unroll
            for (int mt = 0; mt < 4; mt++)
#pragma unroll
                for (int nt = 0; nt < 8; nt++)
                    mma_f16(acc[mt][nt], af[mt], bf[nt]);
        }
    }

    ll cbase = zb * sCb;
    float* Cf = (float*)Cm + cbase;
    __half* Ch = (__half*)Cm + cbase;
#pragma unroll
    for (int mt = 0; mt < 4; mt++) {
#pragma unroll
        for (int hf = 0; hf < 2; hf++) {
            int m = m0 + wm * 64 + mt * 16 + g + hf * 8;
            if (m >= M) continue;
            float bm = (biasMode == 2) ? bias[m] : 0.f;
#pragma unroll
            for (int nt = 0; nt < 8; nt++) {
#pragma unroll
                for (int e = 0; e < 2; e++) {
                    int n = n0 + wn * 64 + nt * 8 + c * 2 + e;
                    if (n >= N) continue;
                    float v = acc[mt][nt][hf * 2 + e] * alpha + bm;
                    if (biasMode == 1) v += bias[n];
                    if (act) v = v * normcdff(v);
                    if (outHalf) Ch[(ll)m * ldc + n] = __float2half_rn(v);
                    else         Cf[(ll)m * ldc + n] = v;
                }
            }
        }
    }
}

// ================= fused flash attention (packed qkv, row stride 3*II) ==========
__global__ void __launch_bounds__(256, 1)
flash_attn_kernel(const __half* __restrict__ qkv, __half* __restrict__ Og)
{
    extern __shared__ __half fsm[];
    __half* sQ = fsm;
    __half* sK = fsm + FA_TILE;
    __half* sV = fsm + FA_TILE * (1 + FA_NST);
    uint32_t suQ = smem_u32(sQ), suK = smem_u32(sK), suV = smem_u32(sV);

    int tid = threadIdx.x, lane = tid & 31, wid = tid >> 5;
    int g = lane >> 2, c = lane & 3;
    int bh = blockIdx.y;
    int b = bh / HH, h = bh % HH;
    const __half* Qb = qkv + (ll)b * TT * S3 + h * DH;
    const __half* Kb = Qb + II;
    const __half* Vb = Qb + 2 * II;
    int q0 = blockIdx.x * FA_BR;

    int lrow = tid >> 1;
    int lseg = (tid & 1) * 32;

    {
        const __half* src = Qb + (ll)(q0 + lrow) * S3 + lseg;
        uint32_t dst = suQ + (uint32_t)(lrow * QROW + lseg) * 2;
        cp16(dst, src); cp16(dst + 16, src + 8); cp16(dst + 32, src + 16); cp16(dst + 48, src + 24);
    }
    auto load_kv = [&](int blk, int slot) {
        const __half* ks = Kb + (ll)(blk * FA_BC + lrow) * S3 + lseg;
        const __half* vs = Vb + (ll)(blk * FA_BC + lrow) * S3 + lseg;
        uint32_t kd = suK + (uint32_t)(slot * FA_TILE + lrow * QROW + lseg) * 2;
        uint32_t vd = suV + (uint32_t)(slot * FA_TILE + lrow * QROW + lseg) * 2;
        cp16(kd, ks); cp16(kd + 16, ks + 8); cp16(kd + 32, ks + 16); cp16(kd + 48, ks + 24);
        cp16(vd, vs); cp16(vd + 16, vs + 8); cp16(vd + 32, vs + 16); cp16(vd + 48, vs + 24);
    };

    load_kv(0, 0);
    CP_COMMIT();
    load_kv(1, 1);
    CP_COMMIT();

    uint32_t aQOff = suQ + (uint32_t)((wid * 16 + (lane & 15)) * QROW + ((lane >> 4) * 8)) * 2;
    uint32_t bKOff = (uint32_t)((((lane & 7) + ((lane & 16) >> 1)) * QROW + (lane & 8)) * 2);
    uint32_t bVOff = (uint32_t)(((lane & 15) * QROW + ((lane & 16) >> 1)) * 2);

    const float SC = 0.125f;
    float m0 = -1e30f, m1 = -1e30f, l0 = 0.f, l1 = 0.f;
    float of[8][4];
#pragma unroll
    for (int t = 0; t < 8; t++)
#pragma unroll
        for (int e = 0; e < 4; e++) of[t][e] = 0.f;

    const int NB = TT / FA_BC;
    for (int j = 0; j < NB; j++) {
        CP_WAIT(1);
        __syncthreads();
        if (j + 2 < NB) load_kv(j + 2, (j + 2) % FA_NST);
        CP_COMMIT();

        int slot = j % FA_NST;
        float sf[16][4];
#pragma unroll
        for (int t = 0; t < 16; t++)
#pragma unroll
            for (int e = 0; e < 4; e++) sf[t][e] = 0.f;
        uint32_t kBase = suK + (uint32_t)(slot * FA_TILE) * 2 + bKOff;
#pragma unroll
        for (int kc = 0; kc < 4; kc++) {
            unsigned aF[4];
            ldsm_x4(aF, aQOff + kc * 32);
#pragma unroll
            for (int p = 0; p < 8; p++) {
                unsigned rr[4];
                ldsm_x4(rr, kBase + (uint32_t)(p * 16 * QROW) * 2 + kc * 32);
                unsigned b0[2] = { rr[0], rr[1] }, b1[2] = { rr[2], rr[3] };
                mma_f16(sf[2 * p], aF, b0);
                mma_f16(sf[2 * p + 1], aF, b1);
            }
        }
        float mx0 = -1e30f, mx1 = -1e30f;
#pragma unroll
        for (int t = 0; t < 16; t++) {
            mx0 = fmaxf(mx0, fmaxf(sf[t][0], sf[t][1]));
            mx1 = fmaxf(mx1, fmaxf(sf[t][2], sf[t][3]));
        }
        mx0 = fmaxf(mx0, __shfl_xor_sync(0xffffffffu, mx0, 1));
        mx0 = fmaxf(mx0, __shfl_xor_sync(0xffffffffu, mx0, 2));
        mx1 = fmaxf(mx1, __shfl_xor_sync(0xffffffffu, mx1, 1));
        mx1 = fmaxf(mx1, __shfl_xor_sync(0xffffffffu, mx1, 2));
        float nm0 = fmaxf(m0, mx0), nm1 = fmaxf(m1, mx1);
        float corr0 = __expf((m0 - nm0) * SC), corr1 = __expf((m1 - nm1) * SC);
        m0 = nm0; m1 = nm1;
        l0 *= corr0; l1 *= corr1;
        unsigned pf[16][2];
#pragma unroll
        for (int t = 0; t < 16; t++) {
            float p0 = __expf((sf[t][0] - m0) * SC);
            float p1 = __expf((sf[t][1] - m0) * SC);
            float p2 = __expf((sf[t][2] - m1) * SC);
            float p3 = __expf((sf[t][3] - m1) * SC);
            l0 += p0 + p1; l1 += p2 + p3;
            __half2 h01 = __floats2half2_rn(p0, p1);
            __half2 h23 = __floats2half2_rn(p2, p3);
            pf[t][0] = *(unsigned*)&h01;
            pf[t][1] = *(unsigned*)&h23;
        }
#pragma unroll
        for (int t = 0; t < 8; t++) {
            of[t][0] *= corr0; of[t][1] *= corr0;
            of[t][2] *= corr1; of[t][3] *= corr1;
        }
        uint32_t vBase = suV + (uint32_t)(slot * FA_TILE) * 2 + bVOff;
#pragma unroll
        for (int kc = 0; kc < 8; kc++) {
            unsigned aF[4] = { pf[2 * kc][0], pf[2 * kc][1], pf[2 * kc + 1][0], pf[2 * kc + 1][1] };
#pragma unroll
            for (int p = 0; p < 4; p++) {
                unsigned rr[4];
                ldsm_x4_t(rr, vBase + (uint32_t)(kc * 16 * QROW + p * 16) * 2);
                unsigned b0[2] = { rr[0], rr[1] }, b1[2] = { rr[2], rr[3] };
                mma_f16(of[2 * p], aF, b0);
                mma_f16(of[2 * p + 1], aF, b1);
            }
        }
    }

    l0 += __shfl_xor_sync(0xffffffffu, l0, 1);
    l0 += __shfl_xor_sync(0xffffffffu, l0, 2);
    l1 += __shfl_xor_sync(0xffffffffu, l1, 1);
    l1 += __shfl_xor_sync(0xffffffffu, l1, 2);

    float il0 = 1.f / l0, il1 = 1.f / l1;
    int r0 = q0 + wid * 16 + g;
    __half* o0 = Og + (ll)b * TT * II + (ll)r0 * II + h * DH;
    __half* o1 = o0 + 8 * II;
#pragma unroll
    for (int t = 0; t < 8; t++) {
        __half2 v0 = __floats2half2_rn(of[t][0] * il0, of[t][1] * il0);
        __half2 v1 = __floats2half2_rn(of[t][2] * il1, of[t][3] * il1);
        *(__half2*)(o0 + t * 8 + 2 * c) = v0;
        *(__half2*)(o1 + t * 8 + 2 * c) = v1;
    }
}

// ================= conversions / transposes =====================================
__global__ void f2h_kernel(const float* __restrict__ src, __half* __restrict__ dst, ll n) {
    ll i = (ll)blockIdx.x * blockDim.x + threadIdx.x;
    ll stride = (ll)gridDim.x * blockDim.x;
    for (; i < n; i += stride) dst[i] = __float2half_rn(src[i]);
}

__global__ void wtrans_h_kernel(const float* __restrict__ src, __half* __restrict__ dst,
                                int R, int C, ll sStride, ll dStride)
{
    __shared__ float tile[32][33];
    int zz = blockIdx.z;
    src += zz * sStride;
    dst += zz * dStride;
    int r0 = blockIdx.y * 32, c0 = blockIdx.x * 32;
    int tx = threadIdx.x, ty = threadIdx.y;
#pragma unroll
    for (int i = 0; i < 4; i++) {
        int r = r0 + ty + i * 8, c = c0 + tx;
        if (r < R && c < C) tile[ty + i * 8][tx] = src[(ll)r * C + c];
    }
    __syncthreads();
#pragma unroll
    for (int i = 0; i < 4; i++) {
        int c = c0 + ty + i * 8, r = r0 + tx;
        if (c < C && r < R) dst[(ll)c * R + r] = __float2half_rn(tile[tx][ty + i * 8]);
    }
}

#define CWSEG 512
__global__ void convw_permute_kernel(const float* __restrict__ w, __half* __restrict__ wt,
                                     int M, int Cin)
{
    __shared__ float s[CWSEG * KSZ];
    int o = blockIdx.x;
    int base = blockIdx.y * CWSEG;
    int cnt = Cin - base; if (cnt > CWSEG) cnt = CWSEG;
    const float* wp = w + ((ll)o * Cin + base) * KSZ;
    int n = cnt * KSZ;
    for (int i = threadIdx.x; i < n; i += 256) s[i] = wp[i];
    __syncthreads();
#pragma unroll
    for (int tap = 0; tap < KSZ; tap++)
        for (int ch = threadIdx.x; ch < cnt; ch += 256)
            wt[((ll)tap * M + o) * Cin + base + ch] = __float2half_rn(s[ch * KSZ + tap]);
}

// ================= GroupNorm ====================================================
__global__ void gn_stats_kernel(const float* __restrict__ x, float* __restrict__ stats) {
    __shared__ float rs[256], rq[256];
    int idx = blockIdx.x;
    const float* base = x + (ll)idx * 24 * TT;
    const int n = 24 * TT;
    float s = 0.f, q = 0.f;
    for (int i = threadIdx.x; i < n; i += 256) { float v = base[i]; s += v; q += v * v; }
    rs[threadIdx.x] = s; rq[threadIdx.x] = q; __syncthreads();
    for (int st = 128; st > 0; st >>= 1) {
        if (threadIdx.x < st) { rs[threadIdx.x] += rs[threadIdx.x + st]; rq[threadIdx.x] += rq[threadIdx.x + st]; }
        __syncthreads();
    }
    if (threadIdx.x == 0) {
        float mu = rs[0] / (float)n;
        float var = rq[0] / (float)n - mu * mu;
        stats[idx * 2 + 0] = mu;
        stats[idx * 2 + 1] = rsqrtf(var + 1e-6f);
    }
}

__global__ void gn_apply_kernel(const float* __restrict__ x, const float* __restrict__ stats,
                                const float* __restrict__ gs, const float* __restrict__ gb,
                                __half* __restrict__ gt) {
    int bc = blockIdx.x;
    int b = bc / CC, c = bc % CC;
    int sidx = b * 32 + c / 24;
    float mu = stats[sidx * 2], rstd = stats[sidx * 2 + 1];
    float a = gs[c] * rstd;
    float bias = gb[c] - mu * a;
    const float* xr = x + (ll)bc * TT;
    __half* gr = gt + (ll)b * TT * CC + c;
    for (int t = threadIdx.x; t < TT; t += 256)
        gr[(ll)t * CC] = __float2half_rn(xr[t] * a + bias);
}

// ================= LayerNorm ====================================================
__global__ void ln_kernel(const float* __restrict__ x, const float* __restrict__ sc,
                          const float* __restrict__ bi, __half* __restrict__ y)
{
    __shared__ float red[256];
    int token = blockIdx.x;
    const float* xr = x + (ll)token * II;
    int tid = threadIdx.x;
    float v0 = xr[tid], v1 = xr[tid + 256], v2 = xr[tid + 512];
    red[tid] = v0 + v1 + v2; __syncthreads();
    for (int st = 128; st > 0; st >>= 1) {
        if (tid < st) red[tid] += red[tid + st];
        __syncthreads();
    }
    float mu = red[0] * (1.f / (float)II);
    __syncthreads();
    float d0 = v0 - mu, d1 = v1 - mu, d2 = v2 - mu;
    red[tid] = d0 * d0 + d1 * d1 + d2 * d2; __syncthreads();
    for (int st = 128; st > 0; st >>= 1) {
        if (tid < st) red[tid] += red[tid + st];
        __syncthreads();
    }
    float rstd = rsqrtf(red[0] * (1.f / (float)II) + 1e-5f);
    __half* yr = y + (ll)token * II;
    yr[tid]       = __float2half_rn(d0 * rstd * sc[tid] + bi[tid]);
    yr[tid + 256] = __float2half_rn(d1 * rstd * sc[tid + 256] + bi[tid + 256]);
    yr[tid + 512] = __float2half_rn(d2 * rstd * sc[tid + 512] + bi[tid + 512]);
}

// ================= cross-attention (16 keys, packed kcv) ========================
__global__ void cross_attn_kernel(const __half* __restrict__ q, const __half* __restrict__ kcv,
                                  __half* __restrict__ out)
{
    __shared__ float sq[HH][DH];
    int token = blockIdx.x;
    int b = token / TT;
    int wid = threadIdx.x >> 5, lane = threadIdx.x & 31;
    const __half* qrow = q + (ll)token * II + wid * DH;
    sq[wid][lane] = __half2float(qrow[lane]);
    sq[wid][lane + 32] = __half2float(qrow[lane + 32]);
    __syncwarp();
    const __half* kb = kcv + (ll)b * SS * 2 * II + wid * DH;       // K at col 0
    const __half* vb = kb + II;                                    // V at col II
    float s = -1e30f;
    if (lane < SS) {
        s = 0.f;
        const __half* kr = kb + lane * 2 * II;
#pragma unroll
        for (int d = 0; d < DH; d++) s += sq[wid][d] * __half2float(kr[d]);
        s *= 0.125f;
    }
    float m = s;
    for (int o = 8; o >= 1; o >>= 1) m = fmaxf(m, __shfl_xor_sync(0xffffffffu, m, o));
    float e = (lane < SS) ? expf(s - m) : 0.f;
    float sum = e;
    for (int o = 8; o >= 1; o >>= 1) sum += __shfl_xor_sync(0xffffffffu, sum, o);
    float p = e / sum;
    float o0 = 0.f, o1 = 0.f;
#pragma unroll
    for (int j = 0; j < SS; j++) {
        float pj = __shfl_sync(0xffffffffu, p, j);
        const __half* vr = vb + j * 2 * II;
        o0 += pj * __half2float(vr[lane]);
        o1 += pj * __half2float(vr[lane + 32]);
    }
    __half* orow = out + (ll)token * II + wid * DH;
    orow[lane] = __float2half_rn(o0);
    orow[lane + 32] = __float2half_rn(o1);
}

// ================= final residual ===============================================
__global__ void final_kernel(const float* __restrict__ proj, const float* __restrict__ x,
                             float* __restrict__ out) {
    int bc = blockIdx.x;
    int b = bc / CC, c = bc % CC;
    const float* pr = proj + (ll)b * TT * CC + c;
    const float* xr = x + (ll)bc * TT;
    float* orow = out + (ll)bc * TT;
    for (int t = threadIdx.x; t < TT; t += 256)
        orow[t] = pr[(ll)t * CC] + xr[t];
}

// ================= host orchestration ===========================================
static void gemm_h(const __half* A, ll sAb, ll sAh, int lda,
                   const __half* B, ll sBb, ll sBh, int ldb,
                   void* C, ll sCb, ll sCh, int ldc, int outHalf,
                   const float* bias, int biasMode,
                   const float* res, ll sRb, ll sRh, int ldr,
                   int M, int N, int K, int Kinner,
                   float alpha, int Z, int zdiv, int act)
{
    dim3 grid((N + 127) / 128, (M + 127) / 128, Z);
    gemm_h_kernel<<<grid, 256, GK_SMEM_BYTES>>>(A, sAb, sAh, lda, B, sBb, sBh, ldb,
                                                C, sCb, sCh, ldc, outHalf, bias, res, sRb, sRh, ldr,
                                                M, N, K, Kinner, alpha, zdiv, biasMode, act);
}

static void gemm_big(const __half* A, ll sAb, int lda,
                     const __half* B, ll sBb, int ldb,
                     void* C, ll sCb, int ldc, int outHalf,
                     const float* bias, int biasMode,
                     int M, int N, int K, int Kinner,
                     float alpha, int Z, int act)
{
    dim3 grid((N + 127) / 128, (M + 255) / 256, Z);
    gemm_big_kernel<<<grid, 256, BG_SMEM_BYTES>>>(A, sAb, lda, B, sBb, ldb,
                                                  C, sCb, ldc, outHalf, bias,
                                                  M, N, K, Kinner, alpha, biasMode, act);
}

static void wtrans_h(const float* src, __half* dst, int R, int C, ll sS, ll sD, int Z) {
    dim3 grid((C + 31) / 32, (R + 31) / 32, Z);
    wtrans_h_kernel<<<grid, dim3(32, 8)>>>(src, dst, R, C, sS, sD);
}

extern "C" void kernel_launch(void* const* d_in, const int* in_sizes, int n_in,
                              void* d_out, int out_size)
{
    (void)in_sizes; (void)n_in; (void)out_size;
    const float* x      = (const float*)d_in[0];
    const float* ctx    = (const float*)d_in[1];
    const float* gn_s   = (const float*)d_in[2];
    const float* gn_b   = (const float*)d_in[3];
    const float* pin_w  = (const float*)d_in[4];
    const float* pin_b  = (const float*)d_in[5];
    const float* n1_s   = (const float*)d_in[6];
    const float* n1_b   = (const float*)d_in[7];
    const float* a1_wq  = (const float*)d_in[8];
    const float* a1_wk  = (const float*)d_in[9];
    const float* a1_wv  = (const float*)d_in[10];
    const float* a1_wo  = (const float*)d_in[11];
    const float* a1_bo  = (const float*)d_in[12];
    const float* n2_s   = (const float*)d_in[13];
    const float* n2_b   = (const float*)d_in[14];
    const float* a2_wq  = (const float*)d_in[15];
    const float* a2_wk  = (const float*)d_in[16];
    const float* a2_wv  = (const float*)d_in[17];
    const float* a2_wo  = (const float*)d_in[18];
    const float* a2_bo  = (const float*)d_in[19];
    const float* n3_s   = (const float*)d_in[20];
    const float* n3_b   = (const float*)d_in[21];
    const float* ff1_w  = (const float*)d_in[22];
    const float* ff1_b  = (const float*)d_in[23];
    const float* ff2_w  = (const float*)d_in[24];
    const float* ff2_b  = (const float*)d_in[25];
    const float* pout_w = (const float*)d_in[26];
    const float* pout_b = (const float*)d_in[27];

    cudaFuncSetAttribute(gemm_h_kernel, cudaFuncAttributeMaxDynamicSharedMemorySize,
                         GK_SMEM_BYTES);
    cudaFuncSetAttribute(gemm_big_kernel, cudaFuncAttributeMaxDynamicSharedMemorySize,
                         BG_SMEM_BYTES);
    cudaFuncSetAttribute(flash_attn_kernel, cudaFuncAttributeMaxDynamicSharedMemorySize,
                         FA_SMEM_BYTES);

    __half *gth, *hc, *y, *q, *qkv, *ao, *kcv, *f1, *wT, *w2kv, *pinw, *poutw, *ctxh, *wt1, *wt2;
    float *h, *po, *stats;
    cudaGetSymbolAddress((void**)&gth, g_gth);
    cudaGetSymbolAddress((void**)&h,   g_h);
    cudaGetSymbolAddress((void**)&hc,  g_hc);
    cudaGetSymbolAddress((void**)&y,   g_y);
    cudaGetSymbolAddress((void**)&q,   g_q);
    cudaGetSymbolAddress((void**)&qkv, g_qkv);
    cudaGetSymbolAddress((void**)&ao,  g_ao);
    cudaGetSymbolAddress((void**)&kcv, g_kcv);
    cudaGetSymbolAddress((void**)&f1,  g_f1);
    cudaGetSymbolAddress((void**)&wT,  g_wT);
    cudaGetSymbolAddress((void**)&w2kv, g_w2kv);
    cudaGetSymbolAddress((void**)&pinw,  g_pinw);
    cudaGetSymbolAddress((void**)&poutw, g_poutw);
    cudaGetSymbolAddress((void**)&ctxh,  g_ctxh);
    cudaGetSymbolAddress((void**)&wt1, g_wt1);
    cudaGetSymbolAddress((void**)&wt2, g_wt2);
    cudaGetSymbolAddress((void**)&po,  g_po);
    cudaGetSymbolAddress((void**)&stats, g_gstats);

    const ll TI = (ll)TT * II;
    const ll TC = (ll)TT * CC;
    const ll WS = (ll)II * II;
    const ll W1 = (ll)KSZ * FFD * II;
    const ll W2 = (ll)KSZ * II * FFD;
    const ll KV = 2 * (ll)II * CTXD;       // dense cross K|V slab per depth

    // ---- weight prep ----
    wtrans_h(a1_wq, wT + 0 * WS, II, II, (ll)II * II, 8 * WS, DEPTH);
    wtrans_h(a1_wk, wT + 1 * WS, II, II, (ll)II * II, 8 * WS, DEPTH);
    wtrans_h(a1_wv, wT + 2 * WS, II, II, (ll)II * II, 8 * WS, DEPTH);
    wtrans_h(a1_wo, wT + 3 * WS, II, II, (ll)II * II, 8 * WS, DEPTH);
    wtrans_h(a2_wq, wT + 4 * WS, II, II, (ll)II * II, 8 * WS, DEPTH);
    wtrans_h(a2_wo, wT + 7 * WS, II, II, (ll)II * II, 8 * WS, DEPTH);
    // dense fused cross K|V: dst stride KV per depth; V at offset II*CTXD
    wtrans_h(a2_wk, w2kv,             CTXD, II, (ll)CTXD * II, KV, DEPTH);
    wtrans_h(a2_wv, w2kv + (ll)II * CTXD, CTXD, II, (ll)CTXD * II, KV, DEPTH);
    for (int d = 0; d < DEPTH; d++) {
        dim3 g1(FFD, (II + CWSEG - 1) / CWSEG);
        convw_permute_kernel<<<g1, 256>>>(ff1_w + (ll)d * FFD * II * KSZ, wt1 + d * W1, FFD, II);
        dim3 g2(II, (FFD + CWSEG - 1) / CWSEG);
        convw_permute_kernel<<<g2, 256>>>(ff2_w + (ll)d * II * FFD * KSZ, wt2 + d * W2, II, FFD);
    }
    f2h_kernel<<<512, 256>>>(pin_w,  pinw,  (ll)II * CC);
    f2h_kernel<<<512, 256>>>(pout_w, poutw, (ll)CC * II);
    f2h_kernel<<<64, 256>>>(ctx, ctxh, (ll)BB * SS * CTXD);

    // ---- GroupNorm -> gth ; proj_in -> h (fp32 trunk) ----
    gn_stats_kernel<<<BB * 32, 256>>>(x, stats);
    gn_apply_kernel<<<BB * CC, 256>>>(x, stats, gn_s, gn_b, gth);
    gemm_h(gth, TC, 0, CC, pinw, 0, 0, CC, h, TI, 0, II, 0,
           pin_b, 1, 0, 0, 0, 0, TT, II, CC, 0, 1.f, BB, 1, 0);

    for (int d = 0; d < DEPTH; d++) {
        const __half* wqkvT = wT + (d * 8 + 0) * WS;   // slots 0..2 -> dense [3*II][II]
        const __half* woT   = wT + (d * 8 + 3) * WS;
        const __half* w2qT  = wT + (d * 8 + 4) * WS;
        const __half* w2oT  = wT + (d * 8 + 7) * WS;
        const __half* w2kvT = w2kv + d * KV;           // dense [2*II][CTXD]

        // ---- self attention: fused QKV (big tile) + flash ----
        ln_kernel<<<BB * TT, 256>>>(h, n1_s + d * II, n1_b + d * II, y);
        gemm_big(y, TI, II, wqkvT, 0, II, qkv, (ll)TT * S3, S3, 1,
                 0, 0, TT, 3 * II, II, 0, 1.f, BB, 0);
        flash_attn_kernel<<<dim3(TT / FA_BR, BB * HH), 256, FA_SMEM_BYTES>>>(qkv, ao);
        gemm_h(ao, TI, 0, II, woT, 0, 0, II, h, TI, 0, II, 0,
               a1_bo + d * II, 1, h, TI, 0, II, TT, II, II, 0, 1.f, BB, 1, 0);

        // ---- cross attention (fused KV, dense weight slab) ----
        ln_kernel<<<BB * TT, 256>>>(h, n2_s + d * II, n2_b + d * II, y);
        gemm_h(y, TI, 0, II, w2qT, 0, 0, II, q, TI, 0, II, 1,
               0, 0, 0, 0, 0, 0, TT, II, II, 0, 1.f, BB, 1, 0);
        gemm_h(ctxh, (ll)SS * CTXD, 0, CTXD, w2kvT, 0, 0, CTXD,
               kcv, (ll)SS * 2 * II, 0, 2 * II, 1,
               0, 0, 0, 0, 0, 0, SS, 2 * II, CTXD, 0, 1.f, BB, 1, 0);
        cross_attn_kernel<<<BB * TT, HH * 32>>>(q, kcv, ao);
        gemm_h(ao, TI, 0, II, w2oT, 0, 0, II, h, TI, 0, II, 0,
               a2_bo + d * II, 1, h, TI, 0, II, TT, II, II, 0, 1.f, BB, 1, 0);

        // ---- conv feed-forward: ff1 big tile, ff2 generic (fused residual) ----
        ln_kernel<<<BB * TT, 256>>>(h, n3_s + d * II, n3_b + d * II, y);
        gemm_big(y, TI, II, wt1 + d * W1, 0, II, f1, (ll)TT * FFD, FFD, 1,
                 ff1_b + d * FFD, 1, TT, FFD, II * KSZ, II, 1.f, BB, 1);
        if (d == DEPTH - 1) {
            gemm_h(f1, (ll)TT * FFD, 0, FFD, wt2 + d * W2, 0, 0, FFD, hc, TI, 0, II, 1,
                   ff2_b + d * II, 1, h, TI, 0, II,
                   TT, II, FFD * KSZ, FFD, 1.f, BB, 1, 0);
        } else {
            gemm_h(f1, (ll)TT * FFD, 0, FFD, wt2 + d * W2, 0, 0, FFD, h, TI, 0, II, 0,
                   ff2_b + d * II, 1, h, TI, 0, II,
                   TT, II, FFD * KSZ, FFD, 1.f, BB, 1, 0);
        }
    }

    // ---- proj_out + residual ----
    gemm_h(hc, TI, 0, II, poutw, 0, 0, II, po, TC, 0, CC, 0,
           pout_b, 1, 0, 0, 0, 0, TT, CC, II, 0, 1.f, BB, 1, 0);
    final_kernel<<<BB * CC, 256>>>(po, x, (float*)d_out);
}

// round 13
// speedup vs baseline: 1.1103x; 1.1103x over previous
#include <cuda_runtime.h>
#include <cuda_fp16.h>
#include <math.h>
#include <stdint.h>

#define BB 2
#define CC 768
#define TT 2048
#define II 768
#define HH 12
#define DH 64
#define SS 16
#define CTXD 512
#define FFD 3072
#define DEPTH 2
#define KSZ 9

typedef long long ll;

#define LDS_ROW 40              // halfs per smem tile row (32 + 8 pad)
#define STAGE_HALFS (128 * LDS_ROW)
#define NSTAGE 3
#define GK_SMEM_BYTES (2 * NSTAGE * STAGE_HALFS * 2)

// flash-attention tiles
#define FA_BR 128
#define FA_BC 128
#define QROW 72
#define FA_TILE (128 * QROW)
#define FA_NST 3
#define FA_SMEM_BYTES ((1 + 2 * FA_NST) * FA_TILE * 2)
#define S3 (3 * II)             // packed qkv row stride

// ================= scratch ======================================================
__device__ __half g_gth[BB * (ll)TT * CC];
__device__ float  g_h  [BB * (ll)TT * II];
__device__ __half g_hc [BB * (ll)TT * II];
__device__ __half g_y  [BB * (ll)TT * II];
__device__ __half g_q  [BB * (ll)TT * II];
__device__ __half g_qkv[BB * (ll)TT * S3];
__device__ __half g_ao [BB * (ll)TT * II];
__device__ __half g_kcv[BB * SS * 2 * II];
__device__ __half g_f1 [BB * (ll)TT * FFD];
__device__ float  g_po [BB * (ll)TT * CC];
__device__ __half g_wT [16 * (ll)II * II];
__device__ __half g_w2kv[DEPTH * 2 * (ll)II * CTXD];   // dense fused cross K|V weights
__device__ __half g_pinw [(ll)II * CC];
__device__ __half g_poutw[(ll)CC * II];
__device__ __half g_ctxh [BB * SS * CTXD];
__device__ __half g_wt1[DEPTH * (ll)KSZ * FFD * II];
__device__ __half g_wt2[DEPTH * (ll)KSZ * II * FFD];
__device__ float  g_gstats[BB * 32 * 2];

// ================= helpers ======================================================
__device__ __forceinline__ uint32_t smem_u32(const void* p) {
    uint32_t a;
    asm("{ .reg .u64 t; cvta.to.shared.u64 t, %1; cvt.u32.u64 %0, t; }" : "=r"(a) : "l"(p));
    return a;
}
__device__ __forceinline__ void cp16(uint32_t dst, const void* src) {
    asm volatile("cp.async.cg.shared.global [%0], [%1], 16;" :: "r"(dst), "l"(src));
}
#define CP_COMMIT() asm volatile("cp.async.commit_group;" ::: "memory")
#define CP_WAIT(n)  asm volatile("cp.async.wait_group %0;" :: "n"(n) : "memory")

__device__ __forceinline__ void ldsm_x4(unsigned* r, uint32_t addr) {
    asm volatile("ldmatrix.sync.aligned.m8n8.x4.shared.b16 {%0,%1,%2,%3}, [%4];"
                 : "=r"(r[0]), "=r"(r[1]), "=r"(r[2]), "=r"(r[3]) : "r"(addr));
}
__device__ __forceinline__ void ldsm_x4_t(unsigned* r, uint32_t addr) {
    asm volatile("ldmatrix.sync.aligned.m8n8.x4.trans.shared.b16 {%0,%1,%2,%3}, [%4];"
                 : "=r"(r[0]), "=r"(r[1]), "=r"(r[2]), "=r"(r[3]) : "r"(addr));
}
__device__ __forceinline__ void mma_f16(float* c, const unsigned* a, const unsigned* b) {
    asm volatile(
        "mma.sync.aligned.m16n8k16.row.col.f32.f16.f16.f32 "
        "{%0,%1,%2,%3}, {%4,%5,%6,%7}, {%8,%9}, {%0,%1,%2,%3};"
        : "+f"(c[0]), "+f"(c[1]), "+f"(c[2]), "+f"(c[3])
        : "r"(a[0]), "r"(a[1]), "r"(a[2]), "r"(a[3]), "r"(b[0]), "r"(b[1]));
}

// ================= generic fp16 GEMM (128x128, occupancy 2) =====================
__global__ void __launch_bounds__(256, 2)
gemm_h_kernel(const __half* __restrict__ A, ll sAb, ll sAh, int lda,
              const __half* __restrict__ Bm, ll sBb, ll sBh, int ldb,
              void* __restrict__ Cm, ll sCb, ll sCh, int ldc, int outHalf,
              const float* __restrict__ bias,
              const float* __restrict__ res, ll sRb, ll sRh, int ldr,
              int M, int N, int K, int Kinner,
              float alpha, int zdiv, int biasMode, int act)
{
    extern __shared__ __half dynsm[];
    __half* smA = dynsm;
    __half* smB = dynsm + NSTAGE * STAGE_HALFS;
    uint32_t suA = smem_u32(smA);
    uint32_t suB = smem_u32(smB);

    int tid = threadIdx.x;
    int lane = tid & 31, wid = tid >> 5;
    int wm = wid >> 1, wn = wid & 1;
    int g = lane >> 2, c = lane & 3;
    int z = blockIdx.z, zb = z / zdiv, zh = z % zdiv;
    const __half* Ab = A + zb * sAb + zh * sAh;
    const __half* Bb = Bm + zb * sBb + zh * sBh;
    int m0 = blockIdx.y * 128, n0 = blockIdx.x * 128;
    int lr = tid >> 1;
    int lkh = (tid & 1) * 16;
    ll planeB = (ll)N * Kinner;

    uint32_t aOff = ((uint32_t)((wm * 32 + (lane & 15)) * LDS_ROW + ((lane >> 4) * 8))) * 2;
    uint32_t bOff = ((uint32_t)((wn * 64 + (lane & 7) + ((lane & 16) >> 1)) * LDS_ROW + (lane & 8))) * 2;

    float acc[2][8][4];
#pragma unroll
    for (int i = 0; i < 2; i++)
#pragma unroll
        for (int j = 0; j < 8; j++)
#pragma unroll
            for (int e = 0; e < 4; e++) acc[i][j][e] = 0.f;

    auto issue_chunk = [&](int cidx, int slot) {
        int k0 = cidx * 32;
        int tap = 0, koff = k0, shift = 0;
        if (Kinner > 0) { tap = k0 / Kinner; koff = k0 - tap * Kinner; shift = tap - (KSZ / 2); }
        {
            int m = m0 + lr, sr = m + shift;
            bool ok = (m < M) && (sr >= 0) && (sr < M);
            uint32_t da = suA + (slot * STAGE_HALFS + lr * LDS_ROW + lkh) * 2;
            if (ok) {
                const __half* sp = Ab + (ll)sr * lda + koff + lkh;
                cp16(da, sp);
                cp16(da + 16, sp + 8);
            } else {
                *(uint4*)&smA[slot * STAGE_HALFS + lr * LDS_ROW + lkh] = make_uint4(0, 0, 0, 0);
                *(uint4*)&smA[slot * STAGE_HALFS + lr * LDS_ROW + lkh + 8] = make_uint4(0, 0, 0, 0);
            }
        }
        {
            int n = n0 + lr;
            bool ok = (n < N);
            uint32_t db = suB + (slot * STAGE_HALFS + lr * LDS_ROW + lkh) * 2;
            if (ok) {
                const __half* sp = Bb + (ll)tap * planeB + (ll)n * ldb + koff + lkh;
                cp16(db, sp);
                cp16(db + 16, sp + 8);
            } else {
                *(uint4*)&smB[slot * STAGE_HALFS + lr * LDS_ROW + lkh] = make_uint4(0, 0, 0, 0);
                *(uint4*)&smB[slot * STAGE_HALFS + lr * LDS_ROW + lkh + 8] = make_uint4(0, 0, 0, 0);
            }
        }
    };

    int NC = K / 32;
    issue_chunk(0, 0);
    CP_COMMIT();
    if (NC > 1) issue_chunk(1, 1);
    CP_COMMIT();

    for (int i = 0; i < NC; i++) {
        CP_WAIT(1);
        __syncthreads();
        if (i + 2 < NC) issue_chunk(i + 2, (i + 2) % NSTAGE);
        CP_COMMIT();

        uint32_t aBase = suA + (uint32_t)((i % NSTAGE) * STAGE_HALFS) * 2 + aOff;
        uint32_t bBase = suB + (uint32_t)((i % NSTAGE) * STAGE_HALFS) * 2 + bOff;
#pragma unroll
        for (int ks = 0; ks < 2; ks++) {
            uint32_t kbb = ks * 32;
            unsigned af[2][4], bf[8][2];
#pragma unroll
            for (int mt = 0; mt < 2; mt++)
                ldsm_x4(af[mt], aBase + mt * (16 * LDS_ROW * 2) + kbb);
#pragma unroll
            for (int j = 0; j < 4; j++) {
                unsigned rr[4];
                ldsm_x4(rr, bBase + j * (16 * LDS_ROW * 2) + kbb);
                bf[2 * j][0] = rr[0]; bf[2 * j][1] = rr[1];
                bf[2 * j + 1][0] = rr[2]; bf[2 * j + 1][1] = rr[3];
            }
#pragma unroll
            for (int mt = 0; mt < 2; mt++)
#pragma unroll
                for (int nt = 0; nt < 8; nt++)
                    mma_f16(acc[mt][nt], af[mt], bf[nt]);
        }
    }

    ll cbase = zb * sCb + zh * sCh;
    float* Cf = (float*)Cm + cbase;
    __half* Ch = (__half*)Cm + cbase;
    const float* Rb2 = res ? (res + zb * sRb + zh * sRh) : (const float*)0;
#pragma unroll
    for (int mt = 0; mt < 2; mt++) {
#pragma unroll
        for (int hf = 0; hf < 2; hf++) {
            int m = m0 + wm * 32 + mt * 16 + g + hf * 8;
            if (m >= M) continue;
            float bm = (biasMode == 2) ? bias[m] : 0.f;
            const float* rr = Rb2 ? (Rb2 + (ll)m * ldr) : (const float*)0;
#pragma unroll
            for (int nt = 0; nt < 8; nt++) {
#pragma unroll
                for (int e = 0; e < 2; e++) {
                    int n = n0 + wn * 64 + nt * 8 + c * 2 + e;
                    if (n >= N) continue;
                    float v = acc[mt][nt][hf * 2 + e] * alpha + bm;
                    if (biasMode == 1) v += bias[n];
                    if (rr) v += rr[n];
                    if (act) v = v * normcdff(v);
                    if (outHalf) Ch[(ll)m * ldc + n] = __float2half_rn(v);
                    else         Cf[(ll)m * ldc + n] = v;
                }
            }
        }
    }
}

// ================= fused flash attention (packed qkv, row stride 3*II) ==========
__global__ void __launch_bounds__(256, 1)
flash_attn_kernel(const __half* __restrict__ qkv, __half* __restrict__ Og)
{
    extern __shared__ __half fsm[];
    __half* sQ = fsm;
    __half* sK = fsm + FA_TILE;
    __half* sV = fsm + FA_TILE * (1 + FA_NST);
    uint32_t suQ = smem_u32(sQ), suK = smem_u32(sK), suV = smem_u32(sV);

    int tid = threadIdx.x, lane = tid & 31, wid = tid >> 5;
    int g = lane >> 2, c = lane & 3;
    int bh = blockIdx.y;
    int b = bh / HH, h = bh % HH;
    const __half* Qb = qkv + (ll)b * TT * S3 + h * DH;
    const __half* Kb = Qb + II;
    const __half* Vb = Qb + 2 * II;
    int q0 = blockIdx.x * FA_BR;

    int lrow = tid >> 1;
    int lseg = (tid & 1) * 32;

    {
        const __half* src = Qb + (ll)(q0 + lrow) * S3 + lseg;
        uint32_t dst = suQ + (uint32_t)(lrow * QROW + lseg) * 2;
        cp16(dst, src); cp16(dst + 16, src + 8); cp16(dst + 32, src + 16); cp16(dst + 48, src + 24);
    }
    auto load_kv = [&](int blk, int slot) {
        const __half* ks = Kb + (ll)(blk * FA_BC + lrow) * S3 + lseg;
        const __half* vs = Vb + (ll)(blk * FA_BC + lrow) * S3 + lseg;
        uint32_t kd = suK + (uint32_t)(slot * FA_TILE + lrow * QROW + lseg) * 2;
        uint32_t vd = suV + (uint32_t)(slot * FA_TILE + lrow * QROW + lseg) * 2;
        cp16(kd, ks); cp16(kd + 16, ks + 8); cp16(kd + 32, ks + 16); cp16(kd + 48, ks + 24);
        cp16(vd, vs); cp16(vd + 16, vs + 8); cp16(vd + 32, vs + 16); cp16(vd + 48, vs + 24);
    };

    load_kv(0, 0);
    CP_COMMIT();
    load_kv(1, 1);
    CP_COMMIT();

    uint32_t aQOff = suQ + (uint32_t)((wid * 16 + (lane & 15)) * QROW + ((lane >> 4) * 8)) * 2;
    uint32_t bKOff = (uint32_t)((((lane & 7) + ((lane & 16) >> 1)) * QROW + (lane & 8)) * 2);
    uint32_t bVOff = (uint32_t)(((lane & 15) * QROW + ((lane & 16) >> 1)) * 2);

    const float SC = 0.125f;
    float m0 = -1e30f, m1 = -1e30f, l0 = 0.f, l1 = 0.f;
    float of[8][4];
#pragma unroll
    for (int t = 0; t < 8; t++)
#pragma unroll
        for (int e = 0; e < 4; e++) of[t][e] = 0.f;

    const int NB = TT / FA_BC;
    for (int j = 0; j < NB; j++) {
        CP_WAIT(1);
        __syncthreads();
        if (j + 2 < NB) load_kv(j + 2, (j + 2) % FA_NST);
        CP_COMMIT();

        int slot = j % FA_NST;
        float sf[16][4];
#pragma unroll
        for (int t = 0; t < 16; t++)
#pragma unroll
            for (int e = 0; e < 4; e++) sf[t][e] = 0.f;
        uint32_t kBase = suK + (uint32_t)(slot * FA_TILE) * 2 + bKOff;
#pragma unroll
        for (int kc = 0; kc < 4; kc++) {
            unsigned aF[4];
            ldsm_x4(aF, aQOff + kc * 32);
#pragma unroll
            for (int p = 0; p < 8; p++) {
                unsigned rr[4];
                ldsm_x4(rr, kBase + (uint32_t)(p * 16 * QROW) * 2 + kc * 32);
                unsigned b0[2] = { rr[0], rr[1] }, b1[2] = { rr[2], rr[3] };
                mma_f16(sf[2 * p], aF, b0);
                mma_f16(sf[2 * p + 1], aF, b1);
            }
        }
        float mx0 = -1e30f, mx1 = -1e30f;
#pragma unroll
        for (int t = 0; t < 16; t++) {
            mx0 = fmaxf(mx0, fmaxf(sf[t][0], sf[t][1]));
            mx1 = fmaxf(mx1, fmaxf(sf[t][2], sf[t][3]));
        }
        mx0 = fmaxf(mx0, __shfl_xor_sync(0xffffffffu, mx0, 1));
        mx0 = fmaxf(mx0, __shfl_xor_sync(0xffffffffu, mx0, 2));
        mx1 = fmaxf(mx1, __shfl_xor_sync(0xffffffffu, mx1, 1));
        mx1 = fmaxf(mx1, __shfl_xor_sync(0xffffffffu, mx1, 2));
        float nm0 = fmaxf(m0, mx0), nm1 = fmaxf(m1, mx1);
        float corr0 = __expf((m0 - nm0) * SC), corr1 = __expf((m1 - nm1) * SC);
        m0 = nm0; m1 = nm1;
        l0 *= corr0; l1 *= corr1;
        unsigned pf[16][2];
#pragma unroll
        for (int t = 0; t < 16; t++) {
            float p0 = __expf((sf[t][0] - m0) * SC);
            float p1 = __expf((sf[t][1] - m0) * SC);
            float p2 = __expf((sf[t][2] - m1) * SC);
            float p3 = __expf((sf[t][3] - m1) * SC);
            l0 += p0 + p1; l1 += p2 + p3;
            __half2 h01 = __floats2half2_rn(p0, p1);
            __half2 h23 = __floats2half2_rn(p2, p3);
            pf[t][0] = *(unsigned*)&h01;
            pf[t][1] = *(unsigned*)&h23;
        }
#pragma unroll
        for (int t = 0; t < 8; t++) {
            of[t][0] *= corr0; of[t][1] *= corr0;
            of[t][2] *= corr1; of[t][3] *= corr1;
        }
        uint32_t vBase = suV + (uint32_t)(slot * FA_TILE) * 2 + bVOff;
#pragma unroll
        for (int kc = 0; kc < 8; kc++) {
            unsigned aF[4] = { pf[2 * kc][0], pf[2 * kc][1], pf[2 * kc + 1][0], pf[2 * kc + 1][1] };
#pragma unroll
            for (int p = 0; p < 4; p++) {
                unsigned rr[4];
                ldsm_x4_t(rr, vBase + (uint32_t)(kc * 16 * QROW + p * 16) * 2);
                unsigned b0[2] = { rr[0], rr[1] }, b1[2] = { rr[2], rr[3] };
                mma_f16(of[2 * p], aF, b0);
                mma_f16(of[2 * p + 1], aF, b1);
            }
        }
    }

    l0 += __shfl_xor_sync(0xffffffffu, l0, 1);
    l0 += __shfl_xor_sync(0xffffffffu, l0, 2);
    l1 += __shfl_xor_sync(0xffffffffu, l1, 1);
    l1 += __shfl_xor_sync(0xffffffffu, l1, 2);

    float il0 = 1.f / l0, il1 = 1.f / l1;
    int r0 = q0 + wid * 16 + g;
    __half* o0 = Og + (ll)b * TT * II + (ll)r0 * II + h * DH;
    __half* o1 = o0 + 8 * II;
#pragma unroll
    for (int t = 0; t < 8; t++) {
        __half2 v0 = __floats2half2_rn(of[t][0] * il0, of[t][1] * il0);
        __half2 v1 = __floats2half2_rn(of[t][2] * il1, of[t][3] * il1);
        *(__half2*)(o0 + t * 8 + 2 * c) = v0;
        *(__half2*)(o1 + t * 8 + 2 * c) = v1;
    }
}

// ================= conversions / transposes =====================================
__global__ void f2h_kernel(const float* __restrict__ src, __half* __restrict__ dst, ll n) {
    ll i = (ll)blockIdx.x * blockDim.x + threadIdx.x;
    ll stride = (ll)gridDim.x * blockDim.x;
    for (; i < n; i += stride) dst[i] = __float2half_rn(src[i]);
}

__global__ void wtrans_h_kernel(const float* __restrict__ src, __half* __restrict__ dst,
                                int R, int C, ll sStride, ll dStride)
{
    __shared__ float tile[32][33];
    int zz = blockIdx.z;
    src += zz * sStride;
    dst += zz * dStride;
    int r0 = blockIdx.y * 32, c0 = blockIdx.x * 32;
    int tx = threadIdx.x, ty = threadIdx.y;
#pragma unroll
    for (int i = 0; i < 4; i++) {
        int r = r0 + ty + i * 8, c = c0 + tx;
        if (r < R && c < C) tile[ty + i * 8][tx] = src[(ll)r * C + c];
    }
    __syncthreads();
#pragma unroll
    for (int i = 0; i < 4; i++) {
        int c = c0 + ty + i * 8, r = r0 + tx;
        if (c < C && r < R) dst[(ll)c * R + r] = __float2half_rn(tile[tx][ty + i * 8]);
    }
}

#define CWSEG 512
__global__ void convw_permute_kernel(const float* __restrict__ w, __half* __restrict__ wt,
                                     int M, int Cin)
{
    __shared__ float s[CWSEG * KSZ];
    int o = blockIdx.x;
    int base = blockIdx.y * CWSEG;
    int cnt = Cin - base; if (cnt > CWSEG) cnt = CWSEG;
    const float* wp = w + ((ll)o * Cin + base) * KSZ;
    int n = cnt * KSZ;
    for (int i = threadIdx.x; i < n; i += 256) s[i] = wp[i];
    __syncthreads();
#pragma unroll
    for (int tap = 0; tap < KSZ; tap++)
        for (int ch = threadIdx.x; ch < cnt; ch += 256)
            wt[((ll)tap * M + o) * Cin + base + ch] = __float2half_rn(s[ch * KSZ + tap]);
}

// ================= GroupNorm ====================================================
__global__ void gn_stats_kernel(const float* __restrict__ x, float* __restrict__ stats) {
    __shared__ float rs[256], rq[256];
    int idx = blockIdx.x;
    const float* base = x + (ll)idx * 24 * TT;
    const int n = 24 * TT;
    float s = 0.f, q = 0.f;
    for (int i = threadIdx.x; i < n; i += 256) { float v = base[i]; s += v; q += v * v; }
    rs[threadIdx.x] = s; rq[threadIdx.x] = q; __syncthreads();
    for (int st = 128; st > 0; st >>= 1) {
        if (threadIdx.x < st) { rs[threadIdx.x] += rs[threadIdx.x + st]; rq[threadIdx.x] += rq[threadIdx.x + st]; }
        __syncthreads();
    }
    if (threadIdx.x == 0) {
        float mu = rs[0] / (float)n;
        float var = rq[0] / (float)n - mu * mu;
        stats[idx * 2 + 0] = mu;
        stats[idx * 2 + 1] = rsqrtf(var + 1e-6f);
    }
}

__global__ void gn_apply_kernel(const float* __restrict__ x, const float* __restrict__ stats,
                                const float* __restrict__ gs, const float* __restrict__ gb,
                                __half* __restrict__ gt) {
    int bc = blockIdx.x;
    int b = bc / CC, c = bc % CC;
    int sidx = b * 32 + c / 24;
    float mu = stats[sidx * 2], rstd = stats[sidx * 2 + 1];
    float a = gs[c] * rstd;
    float bias = gb[c] - mu * a;
    const float* xr = x + (ll)bc * TT;
    __half* gr = gt + (ll)b * TT * CC + c;
    for (int t = threadIdx.x; t < TT; t += 256)
        gr[(ll)t * CC] = __float2half_rn(xr[t] * a + bias);
}

// ================= LayerNorm ====================================================
__global__ void ln_kernel(const float* __restrict__ x, const float* __restrict__ sc,
                          const float* __restrict__ bi, __half* __restrict__ y)
{
    __shared__ float red[256];
    int token = blockIdx.x;
    const float* xr = x + (ll)token * II;
    int tid = threadIdx.x;
    float v0 = xr[tid], v1 = xr[tid + 256], v2 = xr[tid + 512];
    red[tid] = v0 + v1 + v2; __syncthreads();
    for (int st = 128; st > 0; st >>= 1) {
        if (tid < st) red[tid] += red[tid + st];
        __syncthreads();
    }
    float mu = red[0] * (1.f / (float)II);
    __syncthreads();
    float d0 = v0 - mu, d1 = v1 - mu, d2 = v2 - mu;
    red[tid] = d0 * d0 + d1 * d1 + d2 * d2; __syncthreads();
    for (int st = 128; st > 0; st >>= 1) {
        if (tid < st) red[tid] += red[tid + st];
        __syncthreads();
    }
    float rstd = rsqrtf(red[0] * (1.f / (float)II) + 1e-5f);
    __half* yr = y + (ll)token * II;
    yr[tid]       = __float2half_rn(d0 * rstd * sc[tid] + bi[tid]);
    yr[tid + 256] = __float2half_rn(d1 * rstd * sc[tid + 256] + bi[tid + 256]);
    yr[tid + 512] = __float2half_rn(d2 * rstd * sc[tid + 512] + bi[tid + 512]);
}

// ================= cross-attention (16 keys, packed kcv) ========================
__global__ void cross_attn_kernel(const __half* __restrict__ q, const __half* __restrict__ kcv,
                                  __half* __restrict__ out)
{
    __shared__ float sq[HH][DH];
    int token = blockIdx.x;
    int b = token / TT;
    int wid = threadIdx.x >> 5, lane = threadIdx.x & 31;
    const __half* qrow = q + (ll)token * II + wid * DH;
    sq[wid][lane] = __half2float(qrow[lane]);
    sq[wid][lane + 32] = __half2float(qrow[lane + 32]);
    __syncwarp();
    const __half* kb = kcv + (ll)b * SS * 2 * II + wid * DH;       // K at col 0
    const __half* vb = kb + II;                                    // V at col II
    float s = -1e30f;
    if (lane < SS) {
        s = 0.f;
        const __half* kr = kb + lane * 2 * II;
#pragma unroll
        for (int d = 0; d < DH; d++) s += sq[wid][d] * __half2float(kr[d]);
        s *= 0.125f;
    }
    float m = s;
    for (int o = 8; o >= 1; o >>= 1) m = fmaxf(m, __shfl_xor_sync(0xffffffffu, m, o));
    float e = (lane < SS) ? expf(s - m) : 0.f;
    float sum = e;
    for (int o = 8; o >= 1; o >>= 1) sum += __shfl_xor_sync(0xffffffffu, sum, o);
    float p = e / sum;
    float o0 = 0.f, o1 = 0.f;
#pragma unroll
    for (int j = 0; j < SS; j++) {
        float pj = __shfl_sync(0xffffffffu, p, j);
        const __half* vr = vb + j * 2 * II;
        o0 += pj * __half2float(vr[lane]);
        o1 += pj * __half2float(vr[lane + 32]);
    }
    __half* orow = out + (ll)token * II + wid * DH;
    orow[lane] = __float2half_rn(o0);
    orow[lane + 32] = __float2half_rn(o1);
}

// ================= final residual ===============================================
__global__ void final_kernel(const float* __restrict__ proj, const float* __restrict__ x,
                             float* __restrict__ out) {
    int bc = blockIdx.x;
    int b = bc / CC, c = bc % CC;
    const float* pr = proj + (ll)b * TT * CC + c;
    const float* xr = x + (ll)bc * TT;
    float* orow = out + (ll)bc * TT;
    for (int t = threadIdx.x; t < TT; t += 256)
        orow[t] = pr[(ll)t * CC] + xr[t];
}

// ================= host orchestration ===========================================
static void gemm_h(const __half* A, ll sAb, ll sAh, int lda,
                   const __half* B, ll sBb, ll sBh, int ldb,
                   void* C, ll sCb, ll sCh, int ldc, int outHalf,
                   const float* bias, int biasMode,
                   const float* res, ll sRb, ll sRh, int ldr,
                   int M, int N, int K, int Kinner,
                   float alpha, int Z, int zdiv, int act)
{
    dim3 grid((N + 127) / 128, (M + 127) / 128, Z);
    gemm_h_kernel<<<grid, 256, GK_SMEM_BYTES>>>(A, sAb, sAh, lda, B, sBb, sBh, ldb,
                                                C, sCb, sCh, ldc, outHalf, bias, res, sRb, sRh, ldr,
                                                M, N, K, Kinner, alpha, zdiv, biasMode, act);
}

static void wtrans_h(const float* src, __half* dst, int R, int C, ll sS, ll sD, int Z) {
    dim3 grid((C + 31) / 32, (R + 31) / 32, Z);
    wtrans_h_kernel<<<grid, dim3(32, 8)>>>(src, dst, R, C, sS, sD);
}

extern "C" void kernel_launch(void* const* d_in, const int* in_sizes, int n_in,
                              void* d_out, int out_size)
{
    (void)in_sizes; (void)n_in; (void)out_size;
    const float* x      = (const float*)d_in[0];
    const float* ctx    = (const float*)d_in[1];
    const float* gn_s   = (const float*)d_in[2];
    const float* gn_b   = (const float*)d_in[3];
    const float* pin_w  = (const float*)d_in[4];
    const float* pin_b  = (const float*)d_in[5];
    const float* n1_s   = (const float*)d_in[6];
    const float* n1_b   = (const float*)d_in[7];
    const float* a1_wq  = (const float*)d_in[8];
    const float* a1_wk  = (const float*)d_in[9];
    const float* a1_wv  = (const float*)d_in[10];
    const float* a1_wo  = (const float*)d_in[11];
    const float* a1_bo  = (const float*)d_in[12];
    const float* n2_s   = (const float*)d_in[13];
    const float* n2_b   = (const float*)d_in[14];
    const float* a2_wq  = (const float*)d_in[15];
    const float* a2_wk  = (const float*)d_in[16];
    const float* a2_wv  = (const float*)d_in[17];
    const float* a2_wo  = (const float*)d_in[18];
    const float* a2_bo  = (const float*)d_in[19];
    const float* n3_s   = (const float*)d_in[20];
    const float* n3_b   = (const float*)d_in[21];
    const float* ff1_w  = (const float*)d_in[22];
    const float* ff1_b  = (const float*)d_in[23];
    const float* ff2_w  = (const float*)d_in[24];
    const float* ff2_b  = (const float*)d_in[25];
    const float* pout_w = (const float*)d_in[26];
    const float* pout_b = (const float*)d_in[27];

    cudaFuncSetAttribute(gemm_h_kernel, cudaFuncAttributeMaxDynamicSharedMemorySize,
                         GK_SMEM_BYTES);
    cudaFuncSetAttribute(flash_attn_kernel, cudaFuncAttributeMaxDynamicSharedMemorySize,
                         FA_SMEM_BYTES);

    __half *gth, *hc, *y, *q, *qkv, *ao, *kcv, *f1, *wT, *w2kv, *pinw, *poutw, *ctxh, *wt1, *wt2;
    float *h, *po, *stats;
    cudaGetSymbolAddress((void**)&gth, g_gth);
    cudaGetSymbolAddress((void**)&h,   g_h);
    cudaGetSymbolAddress((void**)&hc,  g_hc);
    cudaGetSymbolAddress((void**)&y,   g_y);
    cudaGetSymbolAddress((void**)&q,   g_q);
    cudaGetSymbolAddress((void**)&qkv, g_qkv);
    cudaGetSymbolAddress((void**)&ao,  g_ao);
    cudaGetSymbolAddress((void**)&kcv, g_kcv);
    cudaGetSymbolAddress((void**)&f1,  g_f1);
    cudaGetSymbolAddress((void**)&wT,  g_wT);
    cudaGetSymbolAddress((void**)&w2kv, g_w2kv);
    cudaGetSymbolAddress((void**)&pinw,  g_pinw);
    cudaGetSymbolAddress((void**)&poutw, g_poutw);
    cudaGetSymbolAddress((void**)&ctxh,  g_ctxh);
    cudaGetSymbolAddress((void**)&wt1, g_wt1);
    cudaGetSymbolAddress((void**)&wt2, g_wt2);
    cudaGetSymbolAddress((void**)&po,  g_po);
    cudaGetSymbolAddress((void**)&stats, g_gstats);

    const ll TI = (ll)TT * II;
    const ll TC = (ll)TT * CC;
    const ll WS = (ll)II * II;
    const ll W1 = (ll)KSZ * FFD * II;
    const ll W2 = (ll)KSZ * II * FFD;
    const ll KV = 2 * (ll)II * CTXD;       // dense cross K|V slab per depth

    // ---- weight prep ----
    wtrans_h(a1_wq, wT + 0 * WS, II, II, (ll)II * II, 8 * WS, DEPTH);
    wtrans_h(a1_wk, wT + 1 * WS, II, II, (ll)II * II, 8 * WS, DEPTH);
    wtrans_h(a1_wv, wT + 2 * WS, II, II, (ll)II * II, 8 * WS, DEPTH);
    wtrans_h(a1_wo, wT + 3 * WS, II, II, (ll)II * II, 8 * WS, DEPTH);
    wtrans_h(a2_wq, wT + 4 * WS, II, II, (ll)II * II, 8 * WS, DEPTH);
    wtrans_h(a2_wo, wT + 7 * WS, II, II, (ll)II * II, 8 * WS, DEPTH);
    wtrans_h(a2_wk, w2kv,                 CTXD, II, (ll)CTXD * II, KV, DEPTH);
    wtrans_h(a2_wv, w2kv + (ll)II * CTXD, CTXD, II, (ll)CTXD * II, KV, DEPTH);
    for (int d = 0; d < DEPTH; d++) {
        dim3 g1(FFD, (II + CWSEG - 1) / CWSEG);
        convw_permute_kernel<<<g1, 256>>>(ff1_w + (ll)d * FFD * II * KSZ, wt1 + d * W1, FFD, II);
        dim3 g2(II, (FFD + CWSEG - 1) / CWSEG);
        convw_permute_kernel<<<g2, 256>>>(ff2_w + (ll)d * II * FFD * KSZ, wt2 + d * W2, II, FFD);
    }
    f2h_kernel<<<512, 256>>>(pin_w,  pinw,  (ll)II * CC);
    f2h_kernel<<<512, 256>>>(pout_w, poutw, (ll)CC * II);
    f2h_kernel<<<64, 256>>>(ctx, ctxh, (ll)BB * SS * CTXD);

    // ---- GroupNorm -> gth ; proj_in -> h (fp32 trunk) ----
    gn_stats_kernel<<<BB * 32, 256>>>(x, stats);
    gn_apply_kernel<<<BB * CC, 256>>>(x, stats, gn_s, gn_b, gth);
    gemm_h(gth, TC, 0, CC, pinw, 0, 0, CC, h, TI, 0, II, 0,
           pin_b, 1, 0, 0, 0, 0, TT, II, CC, 0, 1.f, BB, 1, 0);

    for (int d = 0; d < DEPTH; d++) {
        const __half* wqkvT = wT + (d * 8 + 0) * WS;   // slots 0..2 -> dense [3*II][II]
        const __half* woT   = wT + (d * 8 + 3) * WS;
        const __half* w2qT  = wT + (d * 8 + 4) * WS;
        const __half* w2oT  = wT + (d * 8 + 7) * WS;
        const __half* w2kvT = w2kv + d * KV;           // dense [2*II][CTXD]

        // ---- self attention: fused QKV (generic GEMM, N=2304) + flash ----
        ln_kernel<<<BB * TT, 256>>>(h, n1_s + d * II, n1_b + d * II, y);
        gemm_h(y, TI, 0, II, wqkvT, 0, 0, II, qkv, (ll)TT * S3, 0, S3, 1,
               0, 0, 0, 0, 0, 0, TT, 3 * II, II, 0, 1.f, BB, 1, 0);
        flash_attn_kernel<<<dim3(TT / FA_BR, BB * HH), 256, FA_SMEM_BYTES>>>(qkv, ao);
        gemm_h(ao, TI, 0, II, woT, 0, 0, II, h, TI, 0, II, 0,
               a1_bo + d * II, 1, h, TI, 0, II, TT, II, II, 0, 1.f, BB, 1, 0);

        // ---- cross attention (fused KV, dense weight slab) ----
        ln_kernel<<<BB * TT, 256>>>(h, n2_s + d * II, n2_b + d * II, y);
        gemm_h(y, TI, 0, II, w2qT, 0, 0, II, q, TI, 0, II, 1,
               0, 0, 0, 0, 0, 0, TT, II, II, 0, 1.f, BB, 1, 0);
        gemm_h(ctxh, (ll)SS * CTXD, 0, CTXD, w2kvT, 0, 0, CTXD,
               kcv, (ll)SS * 2 * II, 0, 2 * II, 1,
               0, 0, 0, 0, 0, 0, SS, 2 * II, CTXD, 0, 1.f, BB, 1, 0);
        cross_attn_kernel<<<BB * TT, HH * 32>>>(q, kcv, ao);
        gemm_h(ao, TI, 0, II, w2oT, 0, 0, II, h, TI, 0, II, 0,
               a2_bo + d * II, 1, h, TI, 0, II, TT, II, II, 0, 1.f, BB, 1, 0);

        // ---- conv feed-forward (generic GEMM, fused residual) ----
        ln_kernel<<<BB * TT, 256>>>(h, n3_s + d * II, n3_b + d * II, y);
        gemm_h(y, TI, 0, II, wt1 + d * W1, 0, 0, II, f1, (ll)TT * FFD, 0, FFD, 1,
               ff1_b + d * FFD, 1, 0, 0, 0, 0,
               TT, FFD, II * KSZ, II, 1.f, BB, 1, 1);
        if (d == DEPTH - 1) {
            gemm_h(f1, (ll)TT * FFD, 0, FFD, wt2 + d * W2, 0, 0, FFD, hc, TI, 0, II, 1,
                   ff2_b + d * II, 1, h, TI, 0, II,
                   TT, II, FFD * KSZ, FFD, 1.f, BB, 1, 0);
        } else {
            gemm_h(f1, (ll)TT * FFD, 0, FFD, wt2 + d * W2, 0, 0, FFD, h, TI, 0, II, 0,
                   ff2_b + d * II, 1, h, TI, 0, II,
                   TT, II, FFD * KSZ, FFD, 1.f, BB, 1, 0);
        }
    }

    // ---- proj_out + residual ----
    gemm_h(hc, TI, 0, II, poutw, 0, 0, II, po, TC, 0, CC, 0,
           pout_b, 1, 0, 0, 0, 0, TT, CC, II, 0, 1.f, BB, 1, 0);
    final_kernel<<<BB * CC, 256>>>(po, x, (float*)d_out);
}